// round 2
// baseline (speedup 1.0000x reference)
#include <cuda_runtime.h>
#include <math.h>

// Problem constants
#define B_   2
#define G_   8
#define L_   576
#define D_   32
#define NTOK 9216           // B*G*L
#define NT32 (NTOK * 32)

// Scratch (allocation-free rule: __device__ globals)
__device__ float g_Q[NT32];
__device__ float g_K[NT32];
__device__ float g_V[NT32];

// ---------------------------------------------------------------------------
// Kernel 1: grouped 1x1 conv -> Q (pre-scaled), K (+ sinusoidal PE), V
// grid (16, 9), 256 threads. Each block: one (b,h) pair, 64 spatial positions.
// ---------------------------------------------------------------------------
__global__ void __launch_bounds__(256) qkv_kernel(
    const float* __restrict__ x,
    const float* __restrict__ wq,
    const float* __restrict__ wk,
    const float* __restrict__ wv)
{
    const int bh = blockIdx.x;           // 0..15
    const int b  = bh >> 3;
    const int h  = bh & 7;
    const int l0 = blockIdx.y * 64;      // 0..512 step 64

    __shared__ float xs[32][64];

    const int tid = threadIdx.x;
    const float* xbase = x + ((size_t)(b * 256 + h * 32)) * L_ + l0;
    for (int i = tid; i < 32 * 64; i += 256) {
        int dd = i >> 6, ll = i & 63;
        xs[dd][ll] = xbase[dd * L_ + ll];
    }
    __syncthreads();

    const int o    = tid & 31;           // output feature within head
    const int lg   = (tid >> 5) * 8;     // 8 spatial positions per thread
    const int c    = h * 32 + o;         // global channel
    const int nbase = bh * L_ + l0 + lg; // token row base

    #pragma unroll
    for (int m = 0; m < 3; m++) {
        const float* w = (m == 0 ? wq : (m == 1 ? wk : wv)) + (size_t)c * 32;
        float acc[8];
        #pragma unroll
        for (int e = 0; e < 8; e++) acc[e] = 0.f;

        #pragma unroll
        for (int dd = 0; dd < 32; dd++) {
            float wv_ = w[dd];
            float4 a  = *(const float4*)&xs[dd][lg];
            float4 a2 = *(const float4*)&xs[dd][lg + 4];
            acc[0] = fmaf(wv_, a.x,  acc[0]);
            acc[1] = fmaf(wv_, a.y,  acc[1]);
            acc[2] = fmaf(wv_, a.z,  acc[2]);
            acc[3] = fmaf(wv_, a.w,  acc[3]);
            acc[4] = fmaf(wv_, a2.x, acc[4]);
            acc[5] = fmaf(wv_, a2.y, acc[5]);
            acc[6] = fmaf(wv_, a2.z, acc[6]);
            acc[7] = fmaf(wv_, a2.w, acc[7]);
        }

        if (m == 0) {
            // fold softmax scale = sqrt(g / C_OUT) = 1/sqrt(32) into Q
            const float scale = 0.17677669529663688f;
            #pragma unroll
            for (int e = 0; e < 8; e++)
                g_Q[(size_t)(nbase + e) * 32 + o] = acc[e] * scale;
        } else if (m == 1) {
            // sinusoidal PE on keys: i = c & ~1; mirror reference f32 op order,
            // transcendental evaluated in double of the f32-rounded argument.
            int ieven = c & ~1;
            float t = (-9.210340371976184f * (float)ieven) * (1.0f / 256.0f);
            float invf = (float)exp((double)t);
            #pragma unroll
            for (int e = 0; e < 8; e++) {
                float ang = invf * (float)(l0 + lg + e);
                float pe = (c & 1) ? (float)cos((double)ang)
                                   : (float)sin((double)ang);
                g_K[(size_t)(nbase + e) * 32 + o] = acc[e] + pe;
            }
        } else {
            #pragma unroll
            for (int e = 0; e < 8; e++)
                g_V[(size_t)(nbase + e) * 32 + o] = acc[e];
        }
    }
}

// ---------------------------------------------------------------------------
// Kernel 2: flash attention (fp32). 144 blocks x 256 threads.
// Block: 64 query rows. Loop over 144 key tiles of 64.
// Thread (ty,tx) = (tid>>4, tid&15): S microtile rows 4ty..+3, cols 4tx..+3;
// O microtile rows 4ty..+3, feature cols 2tx..2tx+1.
// ---------------------------------------------------------------------------
__global__ void __launch_bounds__(256) attn_kernel(float* __restrict__ out)
{
    __shared__ float Qs[64][32];
    __shared__ float KsT[32][68];   // transposed K tile; stride 68 floats keeps
                                    // 16B alignment for float4 LDS (65 trapped)
    __shared__ float Vs[64][32];
    __shared__ float Ps[64][64];

    const int tid = threadIdx.x;
    const int ty = tid >> 4, tx = tid & 15;
    const int q0 = blockIdx.x * 64;
    const int row0 = 4 * ty;

    for (int i = tid; i < 64 * 32; i += 256) {
        int r = i >> 5, dd = i & 31;
        Qs[r][dd] = g_Q[(size_t)(q0 + r) * 32 + dd];
    }

    float o0[4], o1[4], mrow[4], lsum[4];
    #pragma unroll
    for (int i = 0; i < 4; i++) {
        o0[i] = 0.f; o1[i] = 0.f; mrow[i] = -INFINITY; lsum[i] = 0.f;
    }

    for (int t = 0; t < NTOK / 64; t++) {
        const int k0 = t * 64;
        __syncthreads();   // previous PV readers of Vs/Ps done before overwrite
        for (int i = tid; i < 64 * 32; i += 256) {
            int r = i >> 5, dd = i & 31;
            KsT[dd][r] = g_K[(size_t)(k0 + r) * 32 + dd];
            Vs[r][dd]  = g_V[(size_t)(k0 + r) * 32 + dd];
        }
        __syncthreads();

        // S = Q * K^T  (Q pre-scaled)
        float s[4][4];
        #pragma unroll
        for (int i = 0; i < 4; i++)
            #pragma unroll
            for (int j = 0; j < 4; j++) s[i][j] = 0.f;

        #pragma unroll
        for (int dd = 0; dd < 32; dd++) {
            float4 kv = *(const float4*)&KsT[dd][4 * tx];
            #pragma unroll
            for (int i = 0; i < 4; i++) {
                float qv = Qs[row0 + i][dd];
                s[i][0] = fmaf(qv, kv.x, s[i][0]);
                s[i][1] = fmaf(qv, kv.y, s[i][1]);
                s[i][2] = fmaf(qv, kv.z, s[i][2]);
                s[i][3] = fmaf(qv, kv.w, s[i][3]);
            }
        }

        // online softmax (row stats shared across the 16 tx lanes of a row group)
        #pragma unroll
        for (int i = 0; i < 4; i++) {
            float mx = fmaxf(fmaxf(s[i][0], s[i][1]), fmaxf(s[i][2], s[i][3]));
            #pragma unroll
            for (int off = 1; off < 16; off <<= 1)
                mx = fmaxf(mx, __shfl_xor_sync(0xffffffffu, mx, off));
            float mn = fmaxf(mrow[i], mx);
            float alpha = __expf(mrow[i] - mn);   // first tile: exp(-inf)=0
            mrow[i] = mn;
            lsum[i] *= alpha;
            o0[i] *= alpha;
            o1[i] *= alpha;
            float rs = 0.f;
            #pragma unroll
            for (int j = 0; j < 4; j++) {
                float p = __expf(s[i][j] - mn);
                s[i][j] = p;
                rs += p;
            }
            lsum[i] += rs;   // per-thread partial over own 4 cols
            *(float4*)&Ps[row0 + i][4 * tx] =
                make_float4(s[i][0], s[i][1], s[i][2], s[i][3]);
        }
        __syncthreads();

        // O += P * V
        #pragma unroll 4
        for (int j = 0; j < 64; j++) {
            float2 v = *(const float2*)&Vs[j][2 * tx];
            #pragma unroll
            for (int i = 0; i < 4; i++) {
                float p = Ps[row0 + i][j];
                o0[i] = fmaf(p, v.x, o0[i]);
                o1[i] = fmaf(p, v.y, o1[i]);
            }
        }
    }

    // finalize: reduce lsum across 16 lanes, normalize, scatter to NCHW output
    #pragma unroll
    for (int i = 0; i < 4; i++) {
        float l = lsum[i];
        #pragma unroll
        for (int off = 1; off < 16; off <<= 1)
            l += __shfl_xor_sync(0xffffffffu, l, off);
        float inv = 1.0f / l;
        int n = q0 + row0 + i;
        int b = n / 4608;
        int rem = n - b * 4608;
        int h = rem / 576;
        int lpos = rem - h * 576;
        int chan = h * 32 + 2 * tx;
        out[((size_t)(b * 256 + chan)) * 576 + lpos]     = o0[i] * inv;
        out[((size_t)(b * 256 + chan + 1)) * 576 + lpos] = o1[i] * inv;
    }
}

// ---------------------------------------------------------------------------
extern "C" void kernel_launch(void* const* d_in, const int* in_sizes, int n_in,
                              void* d_out, int out_size)
{
    const float* x  = (const float*)d_in[0];
    const float* wq = (const float*)d_in[1];
    const float* wk = (const float*)d_in[2];
    const float* wv = (const float*)d_in[3];
    float* out = (float*)d_out;

    dim3 g1(16, 9);
    qkv_kernel<<<g1, 256>>>(x, wq, wk, wv);
    attn_kernel<<<NTOK / 64, 256>>>(out);
}

// round 3
// speedup vs baseline: 1.1859x; 1.1859x over previous
#include <cuda_runtime.h>
#include <math.h>

// Problem constants
#define B_   2
#define G_   8
#define L_   576
#define D_   32
#define NTOK 9216           // B*G*L
#define NT32 (NTOK * 32)

// Scratch (allocation-free rule: __device__ globals)
__device__ float g_Q[NT32];
__device__ float g_K[NT32];
__device__ float g_V[NT32];

// ---------------------------------------------------------------------------
// tf32 helpers
// ---------------------------------------------------------------------------
__device__ __forceinline__ unsigned f2tf32(float x) {
    unsigned r;
    asm("cvt.rna.tf32.f32 %0, %1;" : "=r"(r) : "f"(x));
    return r;
}
__device__ __forceinline__ void split_tf32(float x, unsigned& hi, unsigned& lo) {
    hi = f2tf32(x);
    lo = f2tf32(x - __uint_as_float(hi));
}
__device__ __forceinline__ void mma_tf32(float c[4], const unsigned a[4],
                                         unsigned b0, unsigned b1) {
    asm volatile(
        "mma.sync.aligned.m16n8k8.row.col.f32.tf32.tf32.f32 "
        "{%0,%1,%2,%3}, {%4,%5,%6,%7}, {%8,%9}, {%0,%1,%2,%3};"
        : "+f"(c[0]), "+f"(c[1]), "+f"(c[2]), "+f"(c[3])
        : "r"(a[0]), "r"(a[1]), "r"(a[2]), "r"(a[3]), "r"(b0), "r"(b1));
}

// ---------------------------------------------------------------------------
// Kernel 1: grouped 1x1 conv -> Q (pre-scaled), K (+ sinusoidal PE), V
// ---------------------------------------------------------------------------
__global__ void __launch_bounds__(256) qkv_kernel(
    const float* __restrict__ x,
    const float* __restrict__ wq,
    const float* __restrict__ wk,
    const float* __restrict__ wv)
{
    const int bh = blockIdx.x;           // 0..15
    const int b  = bh >> 3;
    const int h  = bh & 7;
    const int l0 = blockIdx.y * 64;      // 0..512 step 64

    __shared__ float xs[32][64];

    const int tid = threadIdx.x;
    const float* xbase = x + ((size_t)(b * 256 + h * 32)) * L_ + l0;
    for (int i = tid; i < 32 * 64; i += 256) {
        int dd = i >> 6, ll = i & 63;
        xs[dd][ll] = xbase[dd * L_ + ll];
    }
    __syncthreads();

    const int o    = tid & 31;
    const int lg   = (tid >> 5) * 8;
    const int c    = h * 32 + o;
    const int nbase = bh * L_ + l0 + lg;

    #pragma unroll
    for (int m = 0; m < 3; m++) {
        const float* w = (m == 0 ? wq : (m == 1 ? wk : wv)) + (size_t)c * 32;
        float acc[8];
        #pragma unroll
        for (int e = 0; e < 8; e++) acc[e] = 0.f;

        #pragma unroll
        for (int dd = 0; dd < 32; dd++) {
            float wv_ = w[dd];
            float4 a  = *(const float4*)&xs[dd][lg];
            float4 a2 = *(const float4*)&xs[dd][lg + 4];
            acc[0] = fmaf(wv_, a.x,  acc[0]);
            acc[1] = fmaf(wv_, a.y,  acc[1]);
            acc[2] = fmaf(wv_, a.z,  acc[2]);
            acc[3] = fmaf(wv_, a.w,  acc[3]);
            acc[4] = fmaf(wv_, a2.x, acc[4]);
            acc[5] = fmaf(wv_, a2.y, acc[5]);
            acc[6] = fmaf(wv_, a2.z, acc[6]);
            acc[7] = fmaf(wv_, a2.w, acc[7]);
        }

        if (m == 0) {
            const float scale = 0.17677669529663688f;  // 1/sqrt(32)
            #pragma unroll
            for (int e = 0; e < 8; e++)
                g_Q[(size_t)(nbase + e) * 32 + o] = acc[e] * scale;
        } else if (m == 1) {
            int ieven = c & ~1;
            float t = (-9.210340371976184f * (float)ieven) * (1.0f / 256.0f);
            float invf = (float)exp((double)t);
            #pragma unroll
            for (int e = 0; e < 8; e++) {
                float ang = invf * (float)(l0 + lg + e);
                float pe = (c & 1) ? (float)cos((double)ang)
                                   : (float)sin((double)ang);
                g_K[(size_t)(nbase + e) * 32 + o] = acc[e] + pe;
            }
        } else {
            #pragma unroll
            for (int e = 0; e < 8; e++)
                g_V[(size_t)(nbase + e) * 32 + o] = acc[e];
        }
    }
}

// ---------------------------------------------------------------------------
// Kernel 2: flash attention, tf32 tensor-core MMA with 3-term error split.
// 144 blocks x 256 threads (8 warps). Block: 64 q rows; loop 144 key tiles.
// Warp w: mw = w>>1 (16 q rows), nw = w&1 (32 S cols / 16 O features).
// ---------------------------------------------------------------------------
__global__ void __launch_bounds__(256) attn_kernel(float* __restrict__ out)
{
    __shared__ float Ks[64][36];    // [key][dd]  stride 36: frag loads conflict-free
    __shared__ float Vs[64][36];    // [key][feat]
    __shared__ float Ps[64][68];    // P round-trip (also Q staging at start)
    __shared__ float smax[2][64];
    __shared__ float ssum[2][64];

    const int tid  = threadIdx.x;
    const int lane = tid & 31;
    const int w    = tid >> 5;
    const int mw   = w >> 1, nw = w & 1;
    const int g    = lane >> 2, t = lane & 3;
    const int q0   = blockIdx.x * 64;
    const int r0   = 16 * mw + g;        // this thread's first row (rows r0, r0+8)

    // ---- stage Q tile, then load register-resident split A-frags ----
    for (int i = tid; i < 512; i += 256) {
        int r = i >> 3, c = (i & 7) * 4;
        *(float4*)&Ps[r][c] = *(const float4*)&g_Q[(size_t)(q0 + r) * 32 + c];
    }
    __syncthreads();

    unsigned qh[4][4], ql[4][4];
    #pragma unroll
    for (int ks = 0; ks < 4; ks++) {
        float a0 = Ps[r0][8 * ks + t];
        float a1 = Ps[r0 + 8][8 * ks + t];
        float a2 = Ps[r0][8 * ks + t + 4];
        float a3 = Ps[r0 + 8][8 * ks + t + 4];
        split_tf32(a0, qh[ks][0], ql[ks][0]);
        split_tf32(a1, qh[ks][1], ql[ks][1]);
        split_tf32(a2, qh[ks][2], ql[ks][2]);
        split_tf32(a3, qh[ks][3], ql[ks][3]);
    }

    float o[2][4];
    #pragma unroll
    for (int i = 0; i < 2; i++)
        #pragma unroll
        for (int j = 0; j < 4; j++) o[i][j] = 0.f;
    float m0 = -INFINITY, m1 = -INFINITY, l0 = 0.f, l1 = 0.f;

    for (int tt = 0; tt < NTOK / 64; tt++) {
        const int k0 = tt * 64;
        __syncthreads();  // sync A: prev tile's readers of Ks/Vs/stats done
        for (int i = tid; i < 512; i += 256) {
            int r = i >> 3, c = (i & 7) * 4;
            *(float4*)&Ks[r][c] = *(const float4*)&g_K[(size_t)(k0 + r) * 32 + c];
            *(float4*)&Vs[r][c] = *(const float4*)&g_V[(size_t)(k0 + r) * 32 + c];
        }
        __syncthreads();  // sync B

        // ---- S = Q K^T (Q pre-scaled), split tf32 ----
        float S[4][4];
        #pragma unroll
        for (int i = 0; i < 4; i++)
            #pragma unroll
            for (int j = 0; j < 4; j++) S[i][j] = 0.f;

        #pragma unroll
        for (int ks = 0; ks < 4; ks++) {
            #pragma unroll
            for (int nt = 0; nt < 4; nt++) {
                int kn = 32 * nw + 8 * nt + g;
                float b0f = Ks[kn][8 * ks + t];
                float b1f = Ks[kn][8 * ks + t + 4];
                unsigned bh0, bl0, bh1, bl1;
                split_tf32(b0f, bh0, bl0);
                split_tf32(b1f, bh1, bl1);
                mma_tf32(S[nt], qh[ks], bh0, bh1);
                mma_tf32(S[nt], qh[ks], bl0, bl1);
                mma_tf32(S[nt], ql[ks], bh0, bh1);
            }
        }

        // ---- online softmax (rows r0, r0+8), cross-warp via stats smem ----
        float vm0 = -INFINITY, vm1 = -INFINITY;
        #pragma unroll
        for (int nt = 0; nt < 4; nt++) {
            vm0 = fmaxf(vm0, fmaxf(S[nt][0], S[nt][1]));
            vm1 = fmaxf(vm1, fmaxf(S[nt][2], S[nt][3]));
        }
        #pragma unroll
        for (int off = 1; off < 4; off <<= 1) {
            vm0 = fmaxf(vm0, __shfl_xor_sync(0xffffffffu, vm0, off));
            vm1 = fmaxf(vm1, __shfl_xor_sync(0xffffffffu, vm1, off));
        }
        if (t == 0) {
            smax[nw][r0]     = vm0;
            smax[nw][r0 + 8] = vm1;
        }
        __syncthreads();  // sync C

        float mn0 = fmaxf(m0, fmaxf(smax[0][r0], smax[1][r0]));
        float mn1 = fmaxf(m1, fmaxf(smax[0][r0 + 8], smax[1][r0 + 8]));
        float al0 = __expf(m0 - mn0);
        float al1 = __expf(m1 - mn1);
        m0 = mn0; m1 = mn1;

        float rs0 = 0.f, rs1 = 0.f;
        #pragma unroll
        for (int nt = 0; nt < 4; nt++) {
            float p00 = __expf(S[nt][0] - mn0);
            float p01 = __expf(S[nt][1] - mn0);
            float p10 = __expf(S[nt][2] - mn1);
            float p11 = __expf(S[nt][3] - mn1);
            rs0 += p00 + p01;
            rs1 += p10 + p11;
            int col = 32 * nw + 8 * nt + 2 * t;
            *(float2*)&Ps[r0][col]     = make_float2(p00, p01);
            *(float2*)&Ps[r0 + 8][col] = make_float2(p10, p11);
        }
        #pragma unroll
        for (int off = 1; off < 4; off <<= 1) {
            rs0 += __shfl_xor_sync(0xffffffffu, rs0, off);
            rs1 += __shfl_xor_sync(0xffffffffu, rs1, off);
        }
        if (t == 0) {
            ssum[nw][r0]     = rs0;
            ssum[nw][r0 + 8] = rs1;
        }
        // rescale O and l
        #pragma unroll
        for (int nt2 = 0; nt2 < 2; nt2++) {
            o[nt2][0] *= al0; o[nt2][1] *= al0;
            o[nt2][2] *= al1; o[nt2][3] *= al1;
        }
        l0 *= al0; l1 *= al1;
        __syncthreads();  // sync D
        l0 += ssum[0][r0] + ssum[1][r0];
        l1 += ssum[0][r0 + 8] + ssum[1][r0 + 8];

        // ---- O += P V, split tf32 ----
        #pragma unroll
        for (int ks = 0; ks < 8; ks++) {
            unsigned ph[4], pl[4];
            split_tf32(Ps[r0][8 * ks + t],         ph[0], pl[0]);
            split_tf32(Ps[r0 + 8][8 * ks + t],     ph[1], pl[1]);
            split_tf32(Ps[r0][8 * ks + t + 4],     ph[2], pl[2]);
            split_tf32(Ps[r0 + 8][8 * ks + t + 4], ph[3], pl[3]);
            #pragma unroll
            for (int nt2 = 0; nt2 < 2; nt2++) {
                int vn = 16 * nw + 8 * nt2 + g;
                float b0f = Vs[8 * ks + t][vn];
                float b1f = Vs[8 * ks + t + 4][vn];
                unsigned vh0, vl0, vh1, vl1;
                split_tf32(b0f, vh0, vl0);
                split_tf32(b1f, vh1, vl1);
                mma_tf32(o[nt2], ph, vh0, vh1);
                mma_tf32(o[nt2], ph, vl0, vl1);
                mma_tf32(o[nt2], pl, vh0, vh1);
            }
        }
    }

    // ---- epilogue: normalize, scatter to NCHW output ----
    float inv0 = 1.0f / l0;
    float inv1 = 1.0f / l1;
    int b = q0 / 4608;
    int rem = q0 - b * 4608;
    int h = rem / 576;
    int lp = (rem - h * 576) + 16 * mw + g;   // spatial pos of row r0
    #pragma unroll
    for (int nt2 = 0; nt2 < 2; nt2++) {
        int f = 16 * nw + 8 * nt2 + 2 * t;
        size_t base = ((size_t)(b * 256 + h * 32 + f)) * 576;
        out[base + lp]             = o[nt2][0] * inv0;
        out[base + 576 + lp]       = o[nt2][1] * inv0;
        out[base + lp + 8]         = o[nt2][2] * inv1;
        out[base + 576 + lp + 8]   = o[nt2][3] * inv1;
    }
}

// ---------------------------------------------------------------------------
extern "C" void kernel_launch(void* const* d_in, const int* in_sizes, int n_in,
                              void* d_out, int out_size)
{
    const float* x  = (const float*)d_in[0];
    const float* wq = (const float*)d_in[1];
    const float* wk = (const float*)d_in[2];
    const float* wv = (const float*)d_in[3];
    float* out = (float*)d_out;

    dim3 g1(16, 9);
    qkv_kernel<<<g1, 256>>>(x, wq, wk, wv);
    attn_kernel<<<NTOK / 64, 256>>>(out);
}

// round 4
// speedup vs baseline: 2.0272x; 1.7094x over previous
#include <cuda_runtime.h>
#include <math.h>

// Problem constants
#define B_   2
#define G_   8
#define L_   576
#define D_   32
#define NTOK 9216           // B*G*L
#define NT32 (NTOK * 32)
#define NTILES 144

// Scratch (allocation-free rule: __device__ globals)
__device__ float g_Q[NT32];
__device__ float g_K[NT32];
__device__ float g_V[NT32];

// ---------------------------------------------------------------------------
// tf32 helpers
// ---------------------------------------------------------------------------
__device__ __forceinline__ unsigned f2tf32(float x) {
    unsigned r;
    asm("cvt.rna.tf32.f32 %0, %1;" : "=r"(r) : "f"(x));
    return r;
}
__device__ __forceinline__ void split_tf32(float x, unsigned& hi, unsigned& lo) {
    hi = f2tf32(x);
    lo = f2tf32(x - __uint_as_float(hi));
}
__device__ __forceinline__ void mma_tf32(float c[4], const unsigned a[4],
                                         unsigned b0, unsigned b1) {
    asm volatile(
        "mma.sync.aligned.m16n8k8.row.col.f32.tf32.tf32.f32 "
        "{%0,%1,%2,%3}, {%4,%5,%6,%7}, {%8,%9}, {%0,%1,%2,%3};"
        : "+f"(c[0]), "+f"(c[1]), "+f"(c[2]), "+f"(c[3])
        : "r"(a[0]), "r"(a[1]), "r"(a[2]), "r"(a[3]), "r"(b0), "r"(b1));
}

// ---------------------------------------------------------------------------
// Kernel 1: grouped 1x1 conv -> Q (pre-scaled), K (+ sinusoidal PE), V
// ---------------------------------------------------------------------------
__global__ void __launch_bounds__(256) qkv_kernel(
    const float* __restrict__ x,
    const float* __restrict__ wq,
    const float* __restrict__ wk,
    const float* __restrict__ wv)
{
    const int bh = blockIdx.x;           // 0..15
    const int b  = bh >> 3;
    const int h  = bh & 7;
    const int l0 = blockIdx.y * 64;      // 0..512 step 64

    __shared__ float xs[32][64];

    const int tid = threadIdx.x;
    const float* xbase = x + ((size_t)(b * 256 + h * 32)) * L_ + l0;
    for (int i = tid; i < 32 * 64; i += 256) {
        int dd = i >> 6, ll = i & 63;
        xs[dd][ll] = xbase[dd * L_ + ll];
    }
    __syncthreads();

    const int o    = tid & 31;
    const int lg   = (tid >> 5) * 8;
    const int c    = h * 32 + o;
    const int nbase = bh * L_ + l0 + lg;

    #pragma unroll
    for (int m = 0; m < 3; m++) {
        const float* w = (m == 0 ? wq : (m == 1 ? wk : wv)) + (size_t)c * 32;
        float acc[8];
        #pragma unroll
        for (int e = 0; e < 8; e++) acc[e] = 0.f;

        #pragma unroll
        for (int dd = 0; dd < 32; dd++) {
            float wv_ = w[dd];
            float4 a  = *(const float4*)&xs[dd][lg];
            float4 a2 = *(const float4*)&xs[dd][lg + 4];
            acc[0] = fmaf(wv_, a.x,  acc[0]);
            acc[1] = fmaf(wv_, a.y,  acc[1]);
            acc[2] = fmaf(wv_, a.z,  acc[2]);
            acc[3] = fmaf(wv_, a.w,  acc[3]);
            acc[4] = fmaf(wv_, a2.x, acc[4]);
            acc[5] = fmaf(wv_, a2.y, acc[5]);
            acc[6] = fmaf(wv_, a2.z, acc[6]);
            acc[7] = fmaf(wv_, a2.w, acc[7]);
        }

        if (m == 0) {
            const float scale = 0.17677669529663688f;  // 1/sqrt(32)
            #pragma unroll
            for (int e = 0; e < 8; e++)
                g_Q[(size_t)(nbase + e) * 32 + o] = acc[e] * scale;
        } else if (m == 1) {
            int ieven = c & ~1;
            float t = (-9.210340371976184f * (float)ieven) * (1.0f / 256.0f);
            float invf = (float)exp((double)t);
            #pragma unroll
            for (int e = 0; e < 8; e++) {
                float ang = invf * (float)(l0 + lg + e);
                float pe = (c & 1) ? (float)cos((double)ang)
                                   : (float)sin((double)ang);
                g_K[(size_t)(nbase + e) * 32 + o] = acc[e] + pe;
            }
        } else {
            #pragma unroll
            for (int e = 0; e < 8; e++)
                g_V[(size_t)(nbase + e) * 32 + o] = acc[e];
        }
    }
}

// ---------------------------------------------------------------------------
// Kernel 2: flash attention, tf32 MMA. 144 blocks x 256 threads (8 warps).
// K pre-split (hi/lo) + V pre-converted to tf32 in smem, cooperatively,
// triple-buffered with register prefetch => ONE __syncthreads per tile.
// Softmax uses deferred-max: P stored as exp(S - vm_own); correction factor
// exp(vm_owner - m_new) folded into PV A-frag loads.
// ---------------------------------------------------------------------------
#define KSTRIDE 36   // (4g+t) conflict-free for QK B loads
#define VSTRIDE 40   // (8t+g) conflict-free for PV B loads
#define PSTRIDE 68
#define SMEM_BYTES (3*2304*4*2 + 3*2560*4 + 4352*4 + 256*4)

__global__ void __launch_bounds__(256) attn_kernel(float* __restrict__ out)
{
    extern __shared__ unsigned char smem_raw[];
    unsigned* Khi  = (unsigned*)smem_raw;        // 3 * 64*36
    unsigned* Klo  = Khi + 3 * 2304;
    unsigned* Vt   = Klo + 3 * 2304;             // 3 * 64*40
    float*    Ps   = (float*)(Vt + 3 * 2560);    // 64*68
    float*    smaxA = Ps + 4352;                 // 2*64
    float*    ssumA = smaxA + 128;               // 2*64

    const int tid  = threadIdx.x;
    const int lane = tid & 31;
    const int w    = tid >> 5;
    const int mw   = w >> 1, nw = w & 1;
    const int g    = lane >> 2, t = lane & 3;
    const int q0   = blockIdx.x * 64;
    const int r0   = 16 * mw + g;

    // prefetch coordinates: thread handles rows pr0, pr0+32, cols pc..pc+3
    const int pr0 = tid >> 3;
    const int pc  = (tid & 7) * 4;

    // ---- stage Q via Ps, build register-resident split A-frags ----
    for (int i = tid; i < 512; i += 256) {
        int r = i >> 3, c = (i & 7) * 4;
        *(float4*)&Ps[r * PSTRIDE + c] =
            *(const float4*)&g_Q[(size_t)(q0 + r) * 32 + c];
    }
    __syncthreads();

    unsigned qh[4][4], ql[4][4];
    #pragma unroll
    for (int ks = 0; ks < 4; ks++) {
        split_tf32(Ps[r0 * PSTRIDE + 8 * ks + t],           qh[ks][0], ql[ks][0]);
        split_tf32(Ps[(r0 + 8) * PSTRIDE + 8 * ks + t],     qh[ks][1], ql[ks][1]);
        split_tf32(Ps[r0 * PSTRIDE + 8 * ks + t + 4],       qh[ks][2], ql[ks][2]);
        split_tf32(Ps[(r0 + 8) * PSTRIDE + 8 * ks + t + 4], qh[ks][3], ql[ks][3]);
    }

    // ---- prefetch tile 0 into buffer 0 ----
    {
        #pragma unroll
        for (int it = 0; it < 2; it++) {
            int r = pr0 + 32 * it;
            float4 kv = *(const float4*)&g_K[(size_t)r * 32 + pc];
            float4 vv = *(const float4*)&g_V[(size_t)r * 32 + pc];
            unsigned kh[4], kl[4], vt[4];
            split_tf32(kv.x, kh[0], kl[0]);
            split_tf32(kv.y, kh[1], kl[1]);
            split_tf32(kv.z, kh[2], kl[2]);
            split_tf32(kv.w, kh[3], kl[3]);
            vt[0] = f2tf32(vv.x); vt[1] = f2tf32(vv.y);
            vt[2] = f2tf32(vv.z); vt[3] = f2tf32(vv.w);
            *(uint4*)&Khi[r * KSTRIDE + pc] = make_uint4(kh[0], kh[1], kh[2], kh[3]);
            *(uint4*)&Klo[r * KSTRIDE + pc] = make_uint4(kl[0], kl[1], kl[2], kl[3]);
            *(uint4*)&Vt[r * VSTRIDE + pc]  = make_uint4(vt[0], vt[1], vt[2], vt[3]);
        }
    }
    __syncthreads();

    float o[2][4];
    #pragma unroll
    for (int i = 0; i < 2; i++)
        #pragma unroll
        for (int j = 0; j < 4; j++) o[i][j] = 0.f;
    float m0 = -INFINITY, m1 = -INFINITY, l0 = 0.f, l1 = 0.f;

    int cur = 0, nxt = 1;
    for (int tt = 0; tt < NTILES; tt++) {
        const unsigned* KhiC = Khi + cur * 2304;
        const unsigned* KloC = Klo + cur * 2304;
        const unsigned* VtC  = Vt  + cur * 2560;

        // ---- issue LDG for tile tt+1 (latency hidden behind QK MMAs) ----
        float4 nk[2], nv[2];
        const bool has_next = (tt + 1 < NTILES);
        if (has_next) {
            int k0n = (tt + 1) * 64;
            #pragma unroll
            for (int it = 0; it < 2; it++) {
                int r = k0n + pr0 + 32 * it;
                nk[it] = *(const float4*)&g_K[(size_t)r * 32 + pc];
                nv[it] = *(const float4*)&g_V[(size_t)r * 32 + pc];
            }
        }

        // ---- S = Q K^T, 3-pass split tf32, B-frags straight from smem ----
        float S[4][4];
        #pragma unroll
        for (int i = 0; i < 4; i++)
            #pragma unroll
            for (int j = 0; j < 4; j++) S[i][j] = 0.f;

        #pragma unroll
        for (int ks = 0; ks < 4; ks++) {
            #pragma unroll
            for (int nt = 0; nt < 4; nt++) {
                int kn = 32 * nw + 8 * nt + g;
                unsigned bh0 = KhiC[kn * KSTRIDE + 8 * ks + t];
                unsigned bh1 = KhiC[kn * KSTRIDE + 8 * ks + t + 4];
                unsigned bl0 = KloC[kn * KSTRIDE + 8 * ks + t];
                unsigned bl1 = KloC[kn * KSTRIDE + 8 * ks + t + 4];
                mma_tf32(S[nt], qh[ks], bh0, bh1);
                mma_tf32(S[nt], ql[ks], bh0, bh1);
                mma_tf32(S[nt], qh[ks], bl0, bl1);
            }
        }

        // ---- convert+store prefetched tile into buffer nxt ----
        if (has_next) {
            unsigned* KhiN = Khi + nxt * 2304;
            unsigned* KloN = Klo + nxt * 2304;
            unsigned* VtN  = Vt  + nxt * 2560;
            #pragma unroll
            for (int it = 0; it < 2; it++) {
                int r = pr0 + 32 * it;
                unsigned kh[4], kl[4], vt[4];
                split_tf32(nk[it].x, kh[0], kl[0]);
                split_tf32(nk[it].y, kh[1], kl[1]);
                split_tf32(nk[it].z, kh[2], kl[2]);
                split_tf32(nk[it].w, kh[3], kl[3]);
                vt[0] = f2tf32(nv[it].x); vt[1] = f2tf32(nv[it].y);
                vt[2] = f2tf32(nv[it].z); vt[3] = f2tf32(nv[it].w);
                *(uint4*)&KhiN[r * KSTRIDE + pc] = make_uint4(kh[0], kh[1], kh[2], kh[3]);
                *(uint4*)&KloN[r * KSTRIDE + pc] = make_uint4(kl[0], kl[1], kl[2], kl[3]);
                *(uint4*)&VtN[r * VSTRIDE + pc]  = make_uint4(vt[0], vt[1], vt[2], vt[3]);
            }
        }

        // ---- softmax partials over this warp's 32 columns ----
        float vm0 = -INFINITY, vm1 = -INFINITY;
        #pragma unroll
        for (int nt = 0; nt < 4; nt++) {
            vm0 = fmaxf(vm0, fmaxf(S[nt][0], S[nt][1]));
            vm1 = fmaxf(vm1, fmaxf(S[nt][2], S[nt][3]));
        }
        #pragma unroll
        for (int off = 1; off < 4; off <<= 1) {
            vm0 = fmaxf(vm0, __shfl_xor_sync(0xffffffffu, vm0, off));
            vm1 = fmaxf(vm1, __shfl_xor_sync(0xffffffffu, vm1, off));
        }

        float rs0 = 0.f, rs1 = 0.f;
        #pragma unroll
        for (int nt = 0; nt < 4; nt++) {
            float p00 = __expf(S[nt][0] - vm0);
            float p01 = __expf(S[nt][1] - vm0);
            float p10 = __expf(S[nt][2] - vm1);
            float p11 = __expf(S[nt][3] - vm1);
            rs0 += p00 + p01;
            rs1 += p10 + p11;
            int col = 32 * nw + 8 * nt + 2 * t;
            *(float2*)&Ps[r0 * PSTRIDE + col]       = make_float2(p00, p01);
            *(float2*)&Ps[(r0 + 8) * PSTRIDE + col] = make_float2(p10, p11);
        }
        #pragma unroll
        for (int off = 1; off < 4; off <<= 1) {
            rs0 += __shfl_xor_sync(0xffffffffu, rs0, off);
            rs1 += __shfl_xor_sync(0xffffffffu, rs1, off);
        }
        if (t == 0) {
            smaxA[nw * 64 + r0]     = vm0;
            smaxA[nw * 64 + r0 + 8] = vm1;
            ssumA[nw * 64 + r0]     = rs0;
            ssumA[nw * 64 + r0 + 8] = rs1;
        }

        __syncthreads();   // THE one barrier per tile

        // ---- combine cross-warp stats; per-(row,owner) correction ----
        float sm00 = smaxA[r0],      sm10 = smaxA[64 + r0];
        float sm01 = smaxA[r0 + 8],  sm11 = smaxA[64 + r0 + 8];
        float mn0 = fmaxf(m0, fmaxf(sm00, sm10));
        float mn1 = fmaxf(m1, fmaxf(sm01, sm11));
        float al0 = __expf(m0 - mn0);
        float al1 = __expf(m1 - mn1);
        float c00 = __expf(sm00 - mn0), c10 = __expf(sm10 - mn0);
        float c01 = __expf(sm01 - mn1), c11 = __expf(sm11 - mn1);
        l0 = l0 * al0 + ssumA[r0] * c00 + ssumA[64 + r0] * c10;
        l1 = l1 * al1 + ssumA[r0 + 8] * c01 + ssumA[64 + r0 + 8] * c11;
        m0 = mn0; m1 = mn1;
        #pragma unroll
        for (int nt2 = 0; nt2 < 2; nt2++) {
            o[nt2][0] *= al0; o[nt2][1] *= al0;
            o[nt2][2] *= al1; o[nt2][3] *= al1;
        }

        // ---- O += P V, single-pass tf32; correction folded into A frags ----
        #pragma unroll
        for (int ks = 0; ks < 8; ks++) {
            float cA = (ks < 4) ? c00 : c10;   // row r0
            float cB = (ks < 4) ? c01 : c11;   // row r0+8
            unsigned a[4];
            a[0] = f2tf32(Ps[r0 * PSTRIDE + 8 * ks + t] * cA);
            a[1] = f2tf32(Ps[(r0 + 8) * PSTRIDE + 8 * ks + t] * cB);
            a[2] = f2tf32(Ps[r0 * PSTRIDE + 8 * ks + t + 4] * cA);
            a[3] = f2tf32(Ps[(r0 + 8) * PSTRIDE + 8 * ks + t + 4] * cB);
            #pragma unroll
            for (int nt2 = 0; nt2 < 2; nt2++) {
                int vn = 16 * nw + 8 * nt2 + g;
                unsigned b0 = VtC[(8 * ks + t) * VSTRIDE + vn];
                unsigned b1 = VtC[(8 * ks + t + 4) * VSTRIDE + vn];
                mma_tf32(o[nt2], a, b0, b1);
            }
        }

        cur = nxt;
        nxt = (nxt == 2) ? 0 : nxt + 1;
    }

    // ---- epilogue: normalize, scatter to NCHW output ----
    float inv0 = 1.0f / l0;
    float inv1 = 1.0f / l1;
    int b = q0 / 4608;
    int rem = q0 - b * 4608;
    int h = rem / 576;
    int lp = (rem - h * 576) + 16 * mw + g;
    #pragma unroll
    for (int nt2 = 0; nt2 < 2; nt2++) {
        int f = 16 * nw + 8 * nt2 + 2 * t;
        size_t base = ((size_t)(b * 256 + h * 32 + f)) * 576;
        out[base + lp]           = o[nt2][0] * inv0;
        out[base + 576 + lp]     = o[nt2][1] * inv0;
        out[base + lp + 8]       = o[nt2][2] * inv1;
        out[base + 576 + lp + 8] = o[nt2][3] * inv1;
    }
}

// ---------------------------------------------------------------------------
extern "C" void kernel_launch(void* const* d_in, const int* in_sizes, int n_in,
                              void* d_out, int out_size)
{
    const float* x  = (const float*)d_in[0];
    const float* wq = (const float*)d_in[1];
    const float* wk = (const float*)d_in[2];
    const float* wv = (const float*)d_in[3];
    float* out = (float*)d_out;

    static bool attr_set = false;
    if (!attr_set) {
        cudaFuncSetAttribute(attn_kernel,
                             cudaFuncAttributeMaxDynamicSharedMemorySize,
                             SMEM_BYTES);
        attr_set = true;
    }

    dim3 g1(16, 9);
    qkv_kernel<<<g1, 256>>>(x, wq, wk, wv);
    attn_kernel<<<NTOK / 64, 256, SMEM_BYTES>>>(out);
}